// round 3
// baseline (speedup 1.0000x reference)
#include <cuda_runtime.h>
#include <math.h>

// Problem constants (fixed by the dataset)
#define BB   8
#define NN   4096
#define KNN  20
#define CO   64
#define M_EDGES (BB*NN*KNN)

#define K1_BLK  128                // 4 warps
#define PTS     32                 // points per block (one per lane)
#define K1_GRID ((BB*NN)/PTS)      // 1024 blocks
#define TILE    1024               // candidate tile (float4 -> 16KB smem)
#define CHUNK   (TILE/4)           // 256 rows per warp per tile

// Scratch (device globals: no runtime allocation allowed)
__device__ float4 g_pos4[BB*NN];           // x,y,z,|p|^2
__device__ int    g_nbr[BB*NN*KNN];        // neighbor indices (2.6 MB)
__device__ float  g_part[K1_GRID*14];      // per-block moment partials
__device__ float  g_A[CO*4];               // folded scale * W
__device__ float  g_C0[CO];                // folded bias

// ---------------------------------------------------------------------------
// Kernel 0: pack positions + squared norm
// ---------------------------------------------------------------------------
__global__ void prep_kernel(const float* __restrict__ pos) {
    int i = blockIdx.x * blockDim.x + threadIdx.x;
    if (i < BB*NN) {
        float x = pos[3*i+0], y = pos[3*i+1], z = pos[3*i+2];
        g_pos4[i] = make_float4(x, y, z, x*x + y*y + z*z);
    }
}

// ---------------------------------------------------------------------------
// Sorted-ascending top-20 insert; caller guarantees d2 < bd[19].
// Early-exit bubble: fully unrolled, static indices (register-resident).
// ---------------------------------------------------------------------------
__device__ __forceinline__ void insert20(float bd[KNN], int bi[KNN],
                                         float d2, int jg) {
    bd[KNN-1] = d2; bi[KNN-1] = jg;
#pragma unroll
    for (int s = KNN-1; s > 0; --s) {
        if (bd[s] >= bd[s-1]) break;
        float td = bd[s]; bd[s] = bd[s-1]; bd[s-1] = td;
        int   ti = bi[s]; bi[s] = bi[s-1]; bi[s-1] = ti;
    }
}

// Sortable pack: (d2 as order-preserving u32) << 32 | idx.
// Keys are globally unique (idx unique), so merge ties cannot occur.
__device__ __forceinline__ unsigned long long packkey(float d2, int idx) {
    unsigned int b = __float_as_uint(d2);
    b ^= (unsigned int)(((int)b >> 31)) | 0x80000000u;  // total order incl. negatives
    return ((unsigned long long)b << 32) | (unsigned int)idx;
}

// ---------------------------------------------------------------------------
// Kernel 1: KNN, 4 warps per 32 points (candidate dim split 4-way).
//           Warp w scans rows [w*256,(w+1)*256) of each tile; lane = point.
//           Per-chunk register top-20 -> u64-key 4-way merge -> moments.
// ---------------------------------------------------------------------------
__global__ void __launch_bounds__(K1_BLK, 8) knn_kernel() {
    __shared__ union ShU {
        float4 sh[TILE];                              // 16 KB (scan phase)
        unsigned long long mg[4][PTS][KNN+1];         // 21.5 KB (merge phase)
    } u;

    const int tid  = threadIdx.x;
    const int warp = tid >> 5;
    const int lane = tid & 31;
    const int p0   = blockIdx.x * PTS;       // first point of this block
    const int b    = p0 / NN;                // whole block is one batch (NN%32==0)
    const int i    = (p0 + lane) - b*NN;     // this lane's batch-local point id

    const float4 pi = g_pos4[p0 + lane];

    float bd[KNN];
    int   bi[KNN];
#pragma unroll
    for (int s = 0; s < KNN; s++) { bd[s] = 1e30f; bi[s] = 0; }

    const int j0 = warp * CHUNK;

    for (int t = 0; t < NN; t += TILE) {
        __syncthreads();
        for (int l = tid; l < TILE; l += K1_BLK)
            u.sh[l] = g_pos4[b*NN + t + l];
        __syncthreads();

#pragma unroll 4
        for (int jj = 0; jj < CHUNK; jj++) {
            float4 p  = u.sh[j0 + jj];                // broadcast: same addr all lanes
            float dot = pi.x*p.x + pi.y*p.y + pi.z*p.z;
            float d2  = (pi.w + p.w) - 2.0f*dot;      // matches reference formula
            int   jg  = t + j0 + jj;
            if (jg == i) d2 = 1e30f;                  // self-exclusion (SEL)
            if (d2 < bd[KNN-1]) insert20(bd, bi, d2, jg);
        }
    }
    __syncthreads();                                   // all warps done reading sh

    // Publish per-chunk sorted lists as packed keys (+ sentinel)
#pragma unroll
    for (int s = 0; s < KNN; s++)
        u.mg[warp][lane][s] = packkey(bd[s], bi[s]);
    u.mg[warp][lane][KNN] = 0xFFFFFFFFFFFFFFFFull;
    __syncthreads();

    // Warp 0: each lane merges its point's 4 sorted lists and computes moments
    float v0=0,v1=0,v2=0,v3=0;
    float pxx=0,pxy=0,pxz=0,pxw=0,pyy=0,pyz=0,pyw=0,pzz=0,pzw=0,pww=0;

    if (tid < PTS) {
        int h0=0, h1=0, h2=0, h3=0;
        int fi[KNN];
#pragma unroll
        for (int s = 0; s < KNN; s++) {
            unsigned long long k0 = u.mg[0][tid][h0];
            unsigned long long k1 = u.mg[1][tid][h1];
            unsigned long long k2 = u.mg[2][tid][h2];
            unsigned long long k3 = u.mg[3][tid][h3];
            unsigned long long ka = k0 < k1 ? k0 : k1;
            unsigned long long kb = k2 < k3 ? k2 : k3;
            unsigned long long km = ka < kb ? ka : kb;
            fi[s] = (int)(km & 0xFFFFFFFFull);
            h0 += (km == k0); h1 += (km == k1);
            h2 += (km == k2); h3 += (km == k3);       // keys unique: exactly one fires
        }

        const int gp = p0 + tid;
        const float4 pc = g_pos4[gp];
#pragma unroll
        for (int s = 0; s < KNN; s++) {
            g_nbr[gp*KNN + s] = fi[s];
            float4 pj = g_pos4[b*NN + fi[s]];
            float dx = pj.x - pc.x;
            float dy = pj.y - pc.y;
            float dz = pj.z - pc.z;
            float dist = sqrtf(dx*dx + dy*dy + dz*dz);
            v0 += dx; v1 += dy; v2 += dz; v3 += dist;
            pxx += dx*dx; pxy += dx*dy; pxz += dx*dz; pxw += dx*dist;
            pyy += dy*dy; pyz += dy*dz; pyw += dy*dist;
            pzz += dz*dz; pzw += dz*dist; pww += dist*dist;
        }
    }

    // Deterministic butterfly reduction across warp 0's 32 lanes
    if (warp == 0) {
        float vals[14] = {v0,v1,v2,v3,pxx,pxy,pxz,pxw,pyy,pyz,pyw,pzz,pzw,pww};
#pragma unroll
        for (int c = 0; c < 14; c++) {
#pragma unroll
            for (int off = 16; off > 0; off >>= 1)
                vals[c] += __shfl_xor_sync(0xFFFFFFFFu, vals[c], off);
        }
        if (lane == 0) {
#pragma unroll
            for (int c = 0; c < 14; c++)
                g_part[blockIdx.x*14 + c] = vals[c];
        }
    }
}

// ---------------------------------------------------------------------------
// Kernel 2: fold BatchNorm into per-channel affine (deterministic, double)
// ---------------------------------------------------------------------------
__global__ void stats_kernel(const float* __restrict__ W,
                             const float* __restrict__ bias,
                             const float* __restrict__ gamma,
                             const float* __restrict__ beta) {
    __shared__ double mom[14];
    __shared__ double part[14][8];
    int tid = threadIdx.x;
    // 14 moments x 8 slices of 128 blocks each (deterministic order)
    if (tid < 112) {
        int m = tid >> 3, sl = tid & 7;
        double a = 0.0;
        for (int blk = sl*128; blk < sl*128 + 128; blk++)
            a += (double)g_part[blk*14 + m];
        part[m][sl] = a;
    }
    __syncthreads();
    if (tid < 14) {
        double a = 0.0;
        for (int sl = 0; sl < 8; sl++) a += part[tid][sl];
        mom[tid] = a;
    }
    __syncthreads();
    if (tid < CO) {
        const double M = (double)M_EDGES;
        double m0=mom[0]/M, m1=mom[1]/M, m2=mom[2]/M, m3=mom[3]/M;
        double Sxx=mom[4]/M, Sxy=mom[5]/M, Sxz=mom[6]/M, Sxw=mom[7]/M;
        double Syy=mom[8]/M, Syz=mom[9]/M, Syw=mom[10]/M;
        double Szz=mom[11]/M, Szw=mom[12]/M, Sww=mom[13]/M;

        double w0 = W[tid*4+0], w1 = W[tid*4+1], w2 = W[tid*4+2], w3 = W[tid*4+3];
        double bb = bias[tid];
        double wm = w0*m0 + w1*m1 + w2*m2 + w3*m3;
        double mu = wm + bb;
        double E2 = w0*w0*Sxx + w1*w1*Syy + w2*w2*Szz + w3*w3*Sww
                  + 2.0*(w0*w1*Sxy + w0*w2*Sxz + w0*w3*Sxw
                       + w1*w2*Syz + w1*w3*Syw + w2*w3*Szw)
                  + 2.0*bb*wm + bb*bb;
        double var   = E2 - mu*mu;
        double scale = (double)gamma[tid] * rsqrt(var + 1e-5);
        g_A[tid*4+0] = (float)(scale * w0);
        g_A[tid*4+1] = (float)(scale * w1);
        g_A[tid*4+2] = (float)(scale * w2);
        g_A[tid*4+3] = (float)(scale * w3);
        g_C0[tid]    = (float)(scale * (bb - mu) + (double)beta[tid]);
    }
}

// ---------------------------------------------------------------------------
// Kernel 3: recompute edge features from indices, affine + relu + mean over k
//           (4 points/block, 64 channels each)
// ---------------------------------------------------------------------------
__global__ void out_kernel(float* __restrict__ out) {
    __shared__ float4 shf[4*KNN];
    const int tid = threadIdx.x;
    const int pt0 = blockIdx.x * 4;
    const int b   = pt0 / NN;

    // Phase 1: 80 threads compute one edge feature each
    if (tid < 4*KNN) {
        const int lp = tid / KNN;          // local point 0..3
        const int s  = tid % KNN;          // neighbor slot
        const int gpt = pt0 + lp;
        const int i  = gpt % NN;
        float4 pi = g_pos4[b*NN + i];
        int    nj = g_nbr[gpt*KNN + s];
        float4 pj = g_pos4[b*NN + nj];
        float dx = pj.x - pi.x;
        float dy = pj.y - pi.y;
        float dz = pj.z - pi.z;
        float dist = sqrtf(dx*dx + dy*dy + dz*dz);
        shf[lp*KNN + s] = make_float4(dx, dy, dz, dist);
    }
    __syncthreads();

    const int lp = tid >> 6;    // local point 0..3
    const int c  = tid & 63;    // channel
    const float a0 = g_A[c*4+0], a1 = g_A[c*4+1], a2 = g_A[c*4+2], a3 = g_A[c*4+3];
    const float c0 = g_C0[c];

    float acc = 0.0f;
#pragma unroll
    for (int s = 0; s < KNN; s++) {
        float4 f = shf[lp*KNN + s];
        float v = a0*f.x + a1*f.y + a2*f.z + a3*f.w + c0;
        acc += fmaxf(v, 0.0f);   // relu; subsequent leaky(0.1) is identity on >=0
    }
    out[(size_t)(pt0 + lp)*CO + c] = acc * (1.0f / KNN);
}

// ---------------------------------------------------------------------------
extern "C" void kernel_launch(void* const* d_in, const int* in_sizes, int n_in,
                              void* d_out, int out_size) {
    const float* pos   = (const float*)d_in[1];
    const float* W     = (const float*)d_in[2];
    const float* bias  = (const float*)d_in[3];
    const float* gamma = (const float*)d_in[4];
    const float* beta  = (const float*)d_in[5];
    float* out = (float*)d_out;

    prep_kernel<<<(BB*NN + 255)/256, 256>>>(pos);
    knn_kernel<<<K1_GRID, K1_BLK>>>();
    stats_kernel<<<1, 128>>>(W, bias, gamma, beta);
    out_kernel<<<(BB*NN)/4, 256>>>(out);
}

// round 4
// speedup vs baseline: 1.4042x; 1.4042x over previous
#include <cuda_runtime.h>
#include <math.h>

// Problem constants (fixed by the dataset)
#define BB   8
#define NN   4096
#define KNN  20
#define CO   64
#define M_EDGES (BB*NN*KNN)

#define K1_BLK  128                // 4 warps
#define PTS     32                 // points per block (one per lane)
#define K1_GRID ((BB*NN)/PTS)      // 1024 blocks
#define TILE    1024               // candidate tile (float4 -> 16KB smem)
#define CHUNK   (TILE/4)           // 256 rows per warp per tile

// Scratch (device globals: no runtime allocation allowed)
__device__ float4 g_pos4[BB*NN];           // x,y,z,|p|^2
__device__ int    g_nbr[BB*NN*KNN];        // neighbor indices (2.6 MB)
__device__ float  g_part[K1_GRID*14];      // per-block moment partials
__device__ float  g_A[CO*4];               // folded scale * W
__device__ float  g_C0[CO];                // folded bias

// ---------------------------------------------------------------------------
// Kernel 0: pack positions + squared norm
// ---------------------------------------------------------------------------
__global__ void prep_kernel(const float* __restrict__ pos) {
    int i = blockIdx.x * blockDim.x + threadIdx.x;
    if (i < BB*NN) {
        float x = pos[3*i+0], y = pos[3*i+1], z = pos[3*i+2];
        g_pos4[i] = make_float4(x, y, z, x*x + y*y + z*z);
    }
}

// ---------------------------------------------------------------------------
// Sorted-ascending top-20 insert; caller guarantees d2 < bd[19].
// Early-exit bubble: fully unrolled, static indices (register-resident).
// ---------------------------------------------------------------------------
__device__ __forceinline__ void insert20(float bd[KNN], int bi[KNN],
                                         float d2, int jg) {
    bd[KNN-1] = d2; bi[KNN-1] = jg;
#pragma unroll
    for (int s = KNN-1; s > 0; --s) {
        if (bd[s] >= bd[s-1]) break;
        float td = bd[s]; bd[s] = bd[s-1]; bd[s-1] = td;
        int   ti = bi[s]; bi[s] = bi[s-1]; bi[s-1] = ti;
    }
}

// Sortable pack: (d2 as order-preserving u32) << 32 | idx.
// Keys are globally unique (idx unique), so merge ties cannot occur.
__device__ __forceinline__ unsigned long long packkey(float d2, int idx) {
    unsigned int b = __float_as_uint(d2);
    b ^= (unsigned int)(((int)b >> 31)) | 0x80000000u;  // total order incl. negatives
    return ((unsigned long long)b << 32) | (unsigned int)idx;
}

// ---------------------------------------------------------------------------
// Kernel 1: KNN, 4 warps per 32 points (candidate dim split 4-way).
//           Warp w scans rows [w*256,(w+1)*256) of each tile; lane = point.
//           Per-chunk register top-20 -> u64-key 4-way merge -> moments.
// NOTE: launch_bounds WITHOUT a min-blocks clause. Forcing 8 blocks/SM
// (round 3) capped regs at 64 and spilled the top-20 arrays to local
// memory -> 10x slowdown. ~80 regs here; occupancy lands at ~6 blocks/SM.
// ---------------------------------------------------------------------------
__global__ void __launch_bounds__(K1_BLK) knn_kernel() {
    __shared__ union ShU {
        float4 sh[TILE];                              // 16 KB (scan phase)
        unsigned long long mg[4][PTS][KNN+1];         // 21.5 KB (merge phase)
    } u;

    const int tid  = threadIdx.x;
    const int warp = tid >> 5;
    const int lane = tid & 31;
    const int p0   = blockIdx.x * PTS;       // first point of this block
    const int b    = p0 / NN;                // whole block is one batch (NN%32==0)
    const int i    = (p0 + lane) - b*NN;     // this lane's batch-local point id

    const float4 pi = g_pos4[p0 + lane];

    float bd[KNN];
    int   bi[KNN];
#pragma unroll
    for (int s = 0; s < KNN; s++) { bd[s] = 1e30f; bi[s] = 0; }

    const int j0 = warp * CHUNK;

    for (int t = 0; t < NN; t += TILE) {
        __syncthreads();
        for (int l = tid; l < TILE; l += K1_BLK)
            u.sh[l] = g_pos4[b*NN + t + l];
        __syncthreads();

#pragma unroll 4
        for (int jj = 0; jj < CHUNK; jj++) {
            float4 p  = u.sh[j0 + jj];                // broadcast: same addr all lanes
            float dot = pi.x*p.x + pi.y*p.y + pi.z*p.z;
            float d2  = (pi.w + p.w) - 2.0f*dot;      // matches reference formula
            int   jg  = t + j0 + jj;
            if (jg == i) d2 = 1e30f;                  // self-exclusion (SEL)
            if (d2 < bd[KNN-1]) insert20(bd, bi, d2, jg);
        }
    }
    __syncthreads();                                   // all warps done reading sh

    // Publish per-chunk sorted lists as packed keys (+ sentinel)
#pragma unroll
    for (int s = 0; s < KNN; s++)
        u.mg[warp][lane][s] = packkey(bd[s], bi[s]);
    u.mg[warp][lane][KNN] = 0xFFFFFFFFFFFFFFFFull;
    __syncthreads();

    // Warp 0: each lane merges its point's 4 sorted lists and computes moments
    float v0=0,v1=0,v2=0,v3=0;
    float pxx=0,pxy=0,pxz=0,pxw=0,pyy=0,pyz=0,pyw=0,pzz=0,pzw=0,pww=0;

    if (tid < PTS) {
        int h0=0, h1=0, h2=0, h3=0;
        int fi[KNN];
#pragma unroll
        for (int s = 0; s < KNN; s++) {
            unsigned long long k0 = u.mg[0][tid][h0];
            unsigned long long k1 = u.mg[1][tid][h1];
            unsigned long long k2 = u.mg[2][tid][h2];
            unsigned long long k3 = u.mg[3][tid][h3];
            unsigned long long ka = k0 < k1 ? k0 : k1;
            unsigned long long kb = k2 < k3 ? k2 : k3;
            unsigned long long km = ka < kb ? ka : kb;
            fi[s] = (int)(km & 0xFFFFFFFFull);
            h0 += (km == k0); h1 += (km == k1);
            h2 += (km == k2); h3 += (km == k3);       // keys unique: exactly one fires
        }

        const int gp = p0 + tid;
        const float4 pc = g_pos4[gp];
#pragma unroll
        for (int s = 0; s < KNN; s++) {
            g_nbr[gp*KNN + s] = fi[s];
            float4 pj = g_pos4[b*NN + fi[s]];
            float dx = pj.x - pc.x;
            float dy = pj.y - pc.y;
            float dz = pj.z - pc.z;
            float dist = sqrtf(dx*dx + dy*dy + dz*dz);
            v0 += dx; v1 += dy; v2 += dz; v3 += dist;
            pxx += dx*dx; pxy += dx*dy; pxz += dx*dz; pxw += dx*dist;
            pyy += dy*dy; pyz += dy*dz; pyw += dy*dist;
            pzz += dz*dz; pzw += dz*dist; pww += dist*dist;
        }
    }

    // Deterministic butterfly reduction across warp 0's 32 lanes
    if (warp == 0) {
        float vals[14] = {v0,v1,v2,v3,pxx,pxy,pxz,pxw,pyy,pyz,pyw,pzz,pzw,pww};
#pragma unroll
        for (int c = 0; c < 14; c++) {
#pragma unroll
            for (int off = 16; off > 0; off >>= 1)
                vals[c] += __shfl_xor_sync(0xFFFFFFFFu, vals[c], off);
        }
        if (lane == 0) {
#pragma unroll
            for (int c = 0; c < 14; c++)
                g_part[blockIdx.x*14 + c] = vals[c];
        }
    }
}

// ---------------------------------------------------------------------------
// Kernel 2: fold BatchNorm into per-channel affine (deterministic, double)
// ---------------------------------------------------------------------------
__global__ void stats_kernel(const float* __restrict__ W,
                             const float* __restrict__ bias,
                             const float* __restrict__ gamma,
                             const float* __restrict__ beta) {
    __shared__ double mom[14];
    __shared__ double part[14][8];
    int tid = threadIdx.x;
    // 14 moments x 8 slices of 128 blocks each (deterministic order)
    if (tid < 112) {
        int m = tid >> 3, sl = tid & 7;
        double a = 0.0;
        for (int blk = sl*128; blk < sl*128 + 128; blk++)
            a += (double)g_part[blk*14 + m];
        part[m][sl] = a;
    }
    __syncthreads();
    if (tid < 14) {
        double a = 0.0;
        for (int sl = 0; sl < 8; sl++) a += part[tid][sl];
        mom[tid] = a;
    }
    __syncthreads();
    if (tid < CO) {
        const double M = (double)M_EDGES;
        double m0=mom[0]/M, m1=mom[1]/M, m2=mom[2]/M, m3=mom[3]/M;
        double Sxx=mom[4]/M, Sxy=mom[5]/M, Sxz=mom[6]/M, Sxw=mom[7]/M;
        double Syy=mom[8]/M, Syz=mom[9]/M, Syw=mom[10]/M;
        double Szz=mom[11]/M, Szw=mom[12]/M, Sww=mom[13]/M;

        double w0 = W[tid*4+0], w1 = W[tid*4+1], w2 = W[tid*4+2], w3 = W[tid*4+3];
        double bb = bias[tid];
        double wm = w0*m0 + w1*m1 + w2*m2 + w3*m3;
        double mu = wm + bb;
        double E2 = w0*w0*Sxx + w1*w1*Syy + w2*w2*Szz + w3*w3*Sww
                  + 2.0*(w0*w1*Sxy + w0*w2*Sxz + w0*w3*Sxw
                       + w1*w2*Syz + w1*w3*Syw + w2*w3*Szw)
                  + 2.0*bb*wm + bb*bb;
        double var   = E2 - mu*mu;
        double scale = (double)gamma[tid] * rsqrt(var + 1e-5);
        g_A[tid*4+0] = (float)(scale * w0);
        g_A[tid*4+1] = (float)(scale * w1);
        g_A[tid*4+2] = (float)(scale * w2);
        g_A[tid*4+3] = (float)(scale * w3);
        g_C0[tid]    = (float)(scale * (bb - mu) + (double)beta[tid]);
    }
}

// ---------------------------------------------------------------------------
// Kernel 3: recompute edge features from indices, affine + relu + mean over k
//           (4 points/block, 64 channels each)
// ---------------------------------------------------------------------------
__global__ void out_kernel(float* __restrict__ out) {
    __shared__ float4 shf[4*KNN];
    const int tid = threadIdx.x;
    const int pt0 = blockIdx.x * 4;
    const int b   = pt0 / NN;

    // Phase 1: 80 threads compute one edge feature each
    if (tid < 4*KNN) {
        const int lp = tid / KNN;          // local point 0..3
        const int s  = tid % KNN;          // neighbor slot
        const int gpt = pt0 + lp;
        const int i  = gpt % NN;
        float4 pi = g_pos4[b*NN + i];
        int    nj = g_nbr[gpt*KNN + s];
        float4 pj = g_pos4[b*NN + nj];
        float dx = pj.x - pi.x;
        float dy = pj.y - pi.y;
        float dz = pj.z - pi.z;
        float dist = sqrtf(dx*dx + dy*dy + dz*dz);
        shf[lp*KNN + s] = make_float4(dx, dy, dz, dist);
    }
    __syncthreads();

    const int lp = tid >> 6;    // local point 0..3
    const int c  = tid & 63;    // channel
    const float a0 = g_A[c*4+0], a1 = g_A[c*4+1], a2 = g_A[c*4+2], a3 = g_A[c*4+3];
    const float c0 = g_C0[c];

    float acc = 0.0f;
#pragma unroll
    for (int s = 0; s < KNN; s++) {
        float4 f = shf[lp*KNN + s];
        float v = a0*f.x + a1*f.y + a2*f.z + a3*f.w + c0;
        acc += fmaxf(v, 0.0f);   // relu; subsequent leaky(0.1) is identity on >=0
    }
    out[(size_t)(pt0 + lp)*CO + c] = acc * (1.0f / KNN);
}

// ---------------------------------------------------------------------------
extern "C" void kernel_launch(void* const* d_in, const int* in_sizes, int n_in,
                              void* d_out, int out_size) {
    const float* pos   = (const float*)d_in[1];
    const float* W     = (const float*)d_in[2];
    const float* bias  = (const float*)d_in[3];
    const float* gamma = (const float*)d_in[4];
    const float* beta  = (const float*)d_in[5];
    float* out = (float*)d_out;

    prep_kernel<<<(BB*NN + 255)/256, 256>>>(pos);
    knn_kernel<<<K1_GRID, K1_BLK>>>();
    stats_kernel<<<1, 128>>>(W, bias, gamma, beta);
    out_kernel<<<(BB*NN)/4, 256>>>(out);
}

// round 5
// speedup vs baseline: 12.5453x; 8.9342x over previous
#include <cuda_runtime.h>
#include <math.h>

// Problem constants (fixed by the dataset)
#define BB   8
#define NN   4096
#define KNN  20
#define CO   64
#define M_EDGES (BB*NN*KNN)

#define K1_BLK  128                // 4 warps
#define PTS     32                 // points per block (one per lane)
#define K1_GRID ((BB*NN)/PTS)      // 1024 blocks
#define TILE    1024               // candidate tile (float4 -> 16KB smem)
#define CHUNK   (TILE/4)           // 256 rows per warp per tile

// Scratch (device globals: no runtime allocation allowed)
__device__ float4 g_pos4[BB*NN];           // x,y,z,|p|^2
__device__ int    g_nbr[BB*NN*KNN];        // neighbor indices (2.6 MB)
__device__ float  g_part[K1_GRID*14];      // per-block moment partials
__device__ float  g_A[CO*4];               // folded scale * W
__device__ float  g_C0[CO];                // folded bias

// ---------------------------------------------------------------------------
// Kernel 0: pack positions + squared norm
// ---------------------------------------------------------------------------
__global__ void prep_kernel(const float* __restrict__ pos) {
    int i = blockIdx.x * blockDim.x + threadIdx.x;
    if (i < BB*NN) {
        float x = pos[3*i+0], y = pos[3*i+1], z = pos[3*i+2];
        g_pos4[i] = make_float4(x, y, z, x*x + y*y + z*z);
    }
}

// Sortable pack: (d2 as order-preserving u32) << 32 | idx.
// Real keys are globally unique (idx unique across disjoint chunks).
__device__ __forceinline__ unsigned long long packkey(float d2, int idx) {
    unsigned int b = __float_as_uint(d2);
    b ^= (unsigned int)(((int)b >> 31)) | 0x80000000u;  // total order incl. negatives
    return ((unsigned long long)b << 32) | (unsigned int)idx;
}

// ---------------------------------------------------------------------------
// Kernel 1: KNN. 4 warps x 32 points; warp w scans rows [w*256,(w+1)*256) of
// each tile (lane = point, broadcast LDS). Register top-20 with BRANCH-FREE
// predicated bubble (NO break, NO dynamic indexing -> stays in registers;
// the R2-R4 break-based insert rolled the loop and spilled to local mem).
// Cross-warp shared threshold per tile prunes insert events exactly.
// ---------------------------------------------------------------------------
__global__ void __launch_bounds__(K1_BLK) knn_kernel() {
    __shared__ union ShU {
        float4 sh[TILE];                              // 16 KB (scan phase)
        unsigned long long mg[4][PTS][KNN+1];         // 21.5 KB (merge phase)
    } u;
    __shared__ float sh_thr[4][PTS];                  // per-warp bd[19] per point

    const int tid  = threadIdx.x;
    const int warp = tid >> 5;
    const int lane = tid & 31;
    const int p0   = blockIdx.x * PTS;       // first point of this block
    const int b    = p0 / NN;                // whole block is one batch (NN%32==0)
    const int i    = (p0 + lane) - b*NN;     // this lane's batch-local point id

    const float4 pi = g_pos4[p0 + lane];

    float bd[KNN];
    int   bi[KNN];
#pragma unroll
    for (int s = 0; s < KNN; s++) { bd[s] = 1e30f; bi[s] = 0; }

    float sthr = 1e30f;          // cross-warp threshold (>= global 20th-best)
    float th   = 1e30f;          // min(sthr, bd[19])
    const int j0 = warp * CHUNK;

    for (int t = 0; t < NN; t += TILE) {
        __syncthreads();                      // prior tile fully consumed
        for (int l = tid; l < TILE; l += K1_BLK)
            u.sh[l] = g_pos4[b*NN + t + l];
        __syncthreads();

#pragma unroll 2
        for (int jj = 0; jj < CHUNK; jj++) {
            float4 p  = u.sh[j0 + jj];                // broadcast: same addr all lanes
            float dot = pi.x*p.x + pi.y*p.y + pi.z*p.z;
            float d2  = (pi.w + p.w) - 2.0f*dot;      // matches reference formula
            int   jg  = t + j0 + jj;
            if (jg == i) d2 = 1e30f;                  // self-exclusion (SEL)
            if (d2 < th) {
                // branch-free predicated bubble (static indices only)
                bd[KNN-1] = d2; bi[KNN-1] = jg;
#pragma unroll
                for (int s = KNN-1; s > 0; --s) {
                    if (bd[s] < bd[s-1]) {
                        float td = bd[s]; bd[s] = bd[s-1]; bd[s-1] = td;
                        int   ti = bi[s]; bi[s] = bi[s-1]; bi[s-1] = ti;
                    }
                }
                th = fminf(sthr, bd[KNN-1]);
            }
        }

        // Publish per-warp 20th-best, take min across the 4 warps.
        // Benign race with next-iteration writers: thresholds only decrease,
        // and ANY observed bd[19] is >= the final global 20th-best (safe prune).
        sh_thr[warp][lane] = bd[KNN-1];
        __syncthreads();
        sthr = fminf(fminf(sh_thr[0][lane], sh_thr[1][lane]),
                     fminf(sh_thr[2][lane], sh_thr[3][lane]));
        th   = fminf(sthr, bd[KNN-1]);
    }
    __syncthreads();                                   // all warps done with sh

    // Publish per-chunk sorted lists as packed keys (+ sentinel)
#pragma unroll
    for (int s = 0; s < KNN; s++)
        u.mg[warp][lane][s] = packkey(bd[s], bi[s]);
    u.mg[warp][lane][KNN] = 0xFFFFFFFFFFFFFFFFull;
    __syncthreads();

    // Warp 0: each lane merges its point's 4 sorted lists and computes moments
    float v0=0,v1=0,v2=0,v3=0;
    float pxx=0,pxy=0,pxz=0,pxw=0,pyy=0,pyz=0,pyw=0,pzz=0,pzw=0,pww=0;

    if (tid < PTS) {
        int h0=0, h1=0, h2=0, h3=0;
        int fi[KNN];
#pragma unroll
        for (int s = 0; s < KNN; s++) {
            unsigned long long k0 = u.mg[0][tid][h0];
            unsigned long long k1 = u.mg[1][tid][h1];
            unsigned long long k2 = u.mg[2][tid][h2];
            unsigned long long k3 = u.mg[3][tid][h3];
            unsigned long long ka = k0 < k1 ? k0 : k1;
            unsigned long long kb = k2 < k3 ? k2 : k3;
            unsigned long long km = ka < kb ? ka : kb;
            fi[s] = (int)(km & 0xFFFFFFFFull);
            h0 += (km == k0); h1 += (km == k1);
            h2 += (km == k2); h3 += (km == k3);       // real keys unique
        }

        const int gp = p0 + tid;
        const float4 pc = g_pos4[gp];
#pragma unroll
        for (int s = 0; s < KNN; s++) {
            g_nbr[gp*KNN + s] = fi[s];
            float4 pj = g_pos4[b*NN + fi[s]];
            float dx = pj.x - pc.x;
            float dy = pj.y - pc.y;
            float dz = pj.z - pc.z;
            float dist = sqrtf(dx*dx + dy*dy + dz*dz);
            v0 += dx; v1 += dy; v2 += dz; v3 += dist;
            pxx += dx*dx; pxy += dx*dy; pxz += dx*dz; pxw += dx*dist;
            pyy += dy*dy; pyz += dy*dz; pyw += dy*dist;
            pzz += dz*dz; pzw += dz*dist; pww += dist*dist;
        }
    }

    // Deterministic butterfly reduction across warp 0's 32 lanes
    if (warp == 0) {
        float vals[14] = {v0,v1,v2,v3,pxx,pxy,pxz,pxw,pyy,pyz,pyw,pzz,pzw,pww};
#pragma unroll
        for (int c = 0; c < 14; c++) {
#pragma unroll
            for (int off = 16; off > 0; off >>= 1)
                vals[c] += __shfl_xor_sync(0xFFFFFFFFu, vals[c], off);
        }
        if (lane == 0) {
#pragma unroll
            for (int c = 0; c < 14; c++)
                g_part[blockIdx.x*14 + c] = vals[c];
        }
    }
}

// ---------------------------------------------------------------------------
// Kernel 2: fold BatchNorm into per-channel affine (deterministic, double)
// ---------------------------------------------------------------------------
__global__ void stats_kernel(const float* __restrict__ W,
                             const float* __restrict__ bias,
                             const float* __restrict__ gamma,
                             const float* __restrict__ beta) {
    __shared__ double mom[14];
    __shared__ double part[14][8];
    int tid = threadIdx.x;
    if (tid < 112) {
        int m = tid >> 3, sl = tid & 7;
        double a = 0.0;
        for (int blk = sl*128; blk < sl*128 + 128; blk++)
            a += (double)g_part[blk*14 + m];
        part[m][sl] = a;
    }
    __syncthreads();
    if (tid < 14) {
        double a = 0.0;
        for (int sl = 0; sl < 8; sl++) a += part[tid][sl];
        mom[tid] = a;
    }
    __syncthreads();
    if (tid < CO) {
        const double M = (double)M_EDGES;
        double m0=mom[0]/M, m1=mom[1]/M, m2=mom[2]/M, m3=mom[3]/M;
        double Sxx=mom[4]/M, Sxy=mom[5]/M, Sxz=mom[6]/M, Sxw=mom[7]/M;
        double Syy=mom[8]/M, Syz=mom[9]/M, Syw=mom[10]/M;
        double Szz=mom[11]/M, Szw=mom[12]/M, Sww=mom[13]/M;

        double w0 = W[tid*4+0], w1 = W[tid*4+1], w2 = W[tid*4+2], w3 = W[tid*4+3];
        double bb = bias[tid];
        double wm = w0*m0 + w1*m1 + w2*m2 + w3*m3;
        double mu = wm + bb;
        double E2 = w0*w0*Sxx + w1*w1*Syy + w2*w2*Szz + w3*w3*Sww
                  + 2.0*(w0*w1*Sxy + w0*w2*Sxz + w0*w3*Sxw
                       + w1*w2*Syz + w1*w3*Syw + w2*w3*Szw)
                  + 2.0*bb*wm + bb*bb;
        double var   = E2 - mu*mu;
        double scale = (double)gamma[tid] * rsqrt(var + 1e-5);
        g_A[tid*4+0] = (float)(scale * w0);
        g_A[tid*4+1] = (float)(scale * w1);
        g_A[tid*4+2] = (float)(scale * w2);
        g_A[tid*4+3] = (float)(scale * w3);
        g_C0[tid]    = (float)(scale * (bb - mu) + (double)beta[tid]);
    }
}

// ---------------------------------------------------------------------------
// Kernel 3: recompute edge features from indices, affine + relu + mean over k
// ---------------------------------------------------------------------------
__global__ void out_kernel(float* __restrict__ out) {
    __shared__ float4 shf[4*KNN];
    const int tid = threadIdx.x;
    const int pt0 = blockIdx.x * 4;
    const int b   = pt0 / NN;

    if (tid < 4*KNN) {
        const int lp = tid / KNN;          // local point 0..3
        const int s  = tid % KNN;          // neighbor slot
        const int gpt = pt0 + lp;
        const int i  = gpt % NN;
        float4 pi = g_pos4[b*NN + i];
        int    nj = g_nbr[gpt*KNN + s];
        float4 pj = g_pos4[b*NN + nj];
        float dx = pj.x - pi.x;
        float dy = pj.y - pi.y;
        float dz = pj.z - pi.z;
        float dist = sqrtf(dx*dx + dy*dy + dz*dz);
        shf[lp*KNN + s] = make_float4(dx, dy, dz, dist);
    }
    __syncthreads();

    const int lp = tid >> 6;    // local point 0..3
    const int c  = tid & 63;    // channel
    const float a0 = g_A[c*4+0], a1 = g_A[c*4+1], a2 = g_A[c*4+2], a3 = g_A[c*4+3];
    const float c0 = g_C0[c];

    float acc = 0.0f;
#pragma unroll
    for (int s = 0; s < KNN; s++) {
        float4 f = shf[lp*KNN + s];
        float v = a0*f.x + a1*f.y + a2*f.z + a3*f.w + c0;
        acc += fmaxf(v, 0.0f);   // relu; subsequent leaky(0.1) is identity on >=0
    }
    out[(size_t)(pt0 + lp)*CO + c] = acc * (1.0f / KNN);
}

// ---------------------------------------------------------------------------
extern "C" void kernel_launch(void* const* d_in, const int* in_sizes, int n_in,
                              void* d_out, int out_size) {
    const float* pos   = (const float*)d_in[1];
    const float* W     = (const float*)d_in[2];
    const float* bias  = (const float*)d_in[3];
    const float* gamma = (const float*)d_in[4];
    const float* beta  = (const float*)d_in[5];
    float* out = (float*)d_out;

    prep_kernel<<<(BB*NN + 255)/256, 256>>>(pos);
    knn_kernel<<<K1_GRID, K1_BLK>>>();
    stats_kernel<<<1, 128>>>(W, bias, gamma, beta);
    out_kernel<<<(BB*NN)/4, 256>>>(out);
}

// round 6
// speedup vs baseline: 13.4197x; 1.0697x over previous
#include <cuda_runtime.h>
#include <math.h>

// Problem constants (fixed by the dataset)
#define BB   8
#define NN   4096
#define KNN  20
#define CO   64
#define M_EDGES (BB*NN*KNN)

#define K1_BLK  128                // 4 warps
#define PTS     32                 // points per block (one per lane)
#define K1_GRID ((BB*NN)/PTS)      // 1024 blocks
#define TILE    1024               // candidate tile (float4 -> 16KB smem)
#define CHUNK   (TILE/4)           // 256 rows per warp per tile

// Scratch (device globals: no runtime allocation allowed)
__device__ float4 g_pos4[BB*NN];           // x,y,z,|p|^2
__device__ int    g_nbr[BB*NN*KNN];        // neighbor indices (2.6 MB)
__device__ float  g_part[K1_GRID*14];      // per-block moment partials
__device__ float  g_A[CO*4];               // folded scale * W
__device__ float  g_C0[CO];                // folded bias

// ---------------------------------------------------------------------------
// Kernel 0: pack positions + squared norm
// ---------------------------------------------------------------------------
__global__ void prep_kernel(const float* __restrict__ pos) {
    int i = blockIdx.x * blockDim.x + threadIdx.x;
    if (i < BB*NN) {
        float x = pos[3*i+0], y = pos[3*i+1], z = pos[3*i+2];
        g_pos4[i] = make_float4(x, y, z, x*x + y*y + z*z);
    }
}

// Sortable pack: (d2 as order-preserving u32) << 32 | idx.
// Real keys are globally unique (idx unique across disjoint chunks).
__device__ __forceinline__ unsigned long long packkey(float d2, int idx) {
    unsigned int b = __float_as_uint(d2);
    b ^= (unsigned int)(((int)b >> 31)) | 0x80000000u;  // total order incl. negatives
    return ((unsigned long long)b << 32) | (unsigned int)idx;
}

// --- 20 named scalar slots: register residency structurally guaranteed -----
#define DECL20 \
    float dd0=1e30f,dd1=1e30f,dd2v=1e30f,dd3=1e30f,dd4=1e30f,dd5=1e30f,   \
          dd6=1e30f,dd7=1e30f,dd8=1e30f,dd9=1e30f,dd10=1e30f,dd11=1e30f,  \
          dd12=1e30f,dd13=1e30f,dd14=1e30f,dd15=1e30f,dd16=1e30f,         \
          dd17=1e30f,dd18=1e30f,dd19=1e30f;                               \
    int ii0=0,ii1=0,ii2=0,ii3=0,ii4=0,ii5=0,ii6=0,ii7=0,ii8=0,ii9=0,      \
        ii10=0,ii11=0,ii12=0,ii13=0,ii14=0,ii15=0,ii16=0,ii17=0,          \
        ii18=0,ii19=0;

// Branchless compare-swap stage: FMNMX x2 + FSETP + SEL x2. NO if{} (avoids
// ptxas BSSY/BSYNC emission), NO array indexing (no local-mem fallback).
#define ST(A,B) {                                                          \
    bool p  = dd##A < dd##B;                                               \
    float lo = fminf(dd##A, dd##B);                                        \
    float hi = fmaxf(dd##A, dd##B);                                        \
    int ilo = p ? ii##A : ii##B;                                           \
    int ihi = p ? ii##B : ii##A;                                           \
    dd##B = lo; dd##A = hi; ii##B = ilo; ii##A = ihi; }

#define BUBBLE20                                                           \
    ST(19,18) ST(18,17) ST(17,16) ST(16,15) ST(15,14) ST(14,13) ST(13,12)  \
    ST(12,11) ST(11,10) ST(10,9)  ST(9,8)   ST(8,7)   ST(7,6)   ST(6,5)    \
    ST(5,4)   ST(4,3)   ST(3,2v)  ST(2v,1)  ST(1,0)

// note: slot 2 is named dd2v/ii2v to avoid clashing with local var names
#define dd2v_ALIAS

#define PUB(S) u.mg[warp][lane][S]

// ---------------------------------------------------------------------------
// Kernel 1: KNN. 4 warps x 32 points; warp w scans rows [w*256,(w+1)*256) of
// each tile (lane = point, broadcast LDS). Register top-20 in NAMED SCALARS,
// branchless select-based bubble. Syncless cross-warp threshold sharing
// every 64 candidates (monotone bounds -> races benign, output invariant).
// ---------------------------------------------------------------------------
__global__ void __launch_bounds__(K1_BLK) knn_kernel() {
    __shared__ union ShU {
        float4 sh[TILE];                              // 16 KB (scan phase)
        unsigned long long mg[4][PTS][KNN+1];         // 21.5 KB (merge phase)
    } u;
    __shared__ float sh_thr[4][PTS];                  // per-warp bd[19] per point

    const int tid  = threadIdx.x;
    const int warp = tid >> 5;
    const int lane = tid & 31;
    const int p0   = blockIdx.x * PTS;       // first point of this block
    const int b    = p0 / NN;                // whole block is one batch (NN%32==0)
    const int i    = (p0 + lane) - b*NN;     // this lane's batch-local point id

    const float4 pi = g_pos4[p0 + lane];

    DECL20
    int ii2v = 0;  // (ii2 alias kept uniform via macro naming below)
    (void)ii2v;

    sh_thr[warp][lane] = 1e30f;
    __syncthreads();

    volatile float (*vthr)[PTS] = (volatile float (*)[PTS])sh_thr;

    float th = 1e30f;                        // current prune threshold
    const int j0 = warp * CHUNK;

    for (int t = 0; t < NN; t += TILE) {
        for (int l = tid; l < TILE; l += K1_BLK)
            u.sh[l] = g_pos4[b*NN + t + l];
        __syncthreads();

        for (int seg = 0; seg < CHUNK; seg += 64) {
            // refresh threshold from all 4 warps (stale reads are safe bounds)
            float s0 = vthr[0][lane], s1 = vthr[1][lane];
            float s2 = vthr[2][lane], s3 = vthr[3][lane];
            float sthr = fminf(fminf(s0, s1), fminf(s2, s3));
            th = fminf(th, sthr);

#pragma unroll 4
            for (int jj = seg; jj < seg + 64; jj++) {
                float4 p  = u.sh[j0 + jj];            // broadcast: same addr all lanes
                float dot = pi.x*p.x + pi.y*p.y + pi.z*p.z;
                float d2  = (pi.w + p.w) - 2.0f*dot;  // matches reference formula
                int   jg  = t + j0 + jj;
                if (jg == i) d2 = 1e30f;              // self-exclusion (SEL)
                if (d2 < th) {
                    dd19 = d2; ii19 = jg;
                    ST(19,18) ST(18,17) ST(17,16) ST(16,15) ST(15,14)
                    ST(14,13) ST(13,12) ST(12,11) ST(11,10) ST(10,9)
                    ST(9,8)   ST(8,7)   ST(7,6)   ST(6,5)   ST(5,4)
                    ST(4,3)   ST(3,2v)  ST(2v,1)  ST(1,0)
                    th = fminf(th, dd19);
                }
            }
            sh_thr[warp][lane] = dd19;                // publish own bound
        }
        __syncthreads();                              // tile fully consumed
    }

    // Publish per-chunk sorted lists as packed keys (+ sentinel)
    PUB(0)=packkey(dd0,ii0);   PUB(1)=packkey(dd1,ii1);
    PUB(2)=packkey(dd2v,ii2v); PUB(3)=packkey(dd3,ii3);
    PUB(4)=packkey(dd4,ii4);   PUB(5)=packkey(dd5,ii5);
    PUB(6)=packkey(dd6,ii6);   PUB(7)=packkey(dd7,ii7);
    PUB(8)=packkey(dd8,ii8);   PUB(9)=packkey(dd9,ii9);
    PUB(10)=packkey(dd10,ii10); PUB(11)=packkey(dd11,ii11);
    PUB(12)=packkey(dd12,ii12); PUB(13)=packkey(dd13,ii13);
    PUB(14)=packkey(dd14,ii14); PUB(15)=packkey(dd15,ii15);
    PUB(16)=packkey(dd16,ii16); PUB(17)=packkey(dd17,ii17);
    PUB(18)=packkey(dd18,ii18); PUB(19)=packkey(dd19,ii19);
    u.mg[warp][lane][KNN] = 0xFFFFFFFFFFFFFFFFull;
    __syncthreads();

    // Warp 0: each lane merges its point's 4 sorted lists and computes moments
    float v0=0,v1=0,v2=0,v3=0;
    float pxx=0,pxy=0,pxz=0,pxw=0,pyy=0,pyz=0,pyw=0,pzz=0,pzw=0,pww=0;

    if (tid < PTS) {
        int h0=0, h1=0, h2=0, h3=0;
        int fi[KNN];
#pragma unroll
        for (int s = 0; s < KNN; s++) {
            unsigned long long k0 = u.mg[0][tid][h0];
            unsigned long long k1 = u.mg[1][tid][h1];
            unsigned long long k2 = u.mg[2][tid][h2];
            unsigned long long k3 = u.mg[3][tid][h3];
            unsigned long long ka = k0 < k1 ? k0 : k1;
            unsigned long long kb = k2 < k3 ? k2 : k3;
            unsigned long long km = ka < kb ? ka : kb;
            fi[s] = (int)(km & 0xFFFFFFFFull);
            h0 += (km == k0); h1 += (km == k1);
            h2 += (km == k2); h3 += (km == k3);       // real keys unique
        }

        const int gp = p0 + tid;
        const float4 pc = g_pos4[gp];
#pragma unroll
        for (int s = 0; s < KNN; s++) {
            g_nbr[gp*KNN + s] = fi[s];
            float4 pj = g_pos4[b*NN + fi[s]];
            float dx = pj.x - pc.x;
            float dy = pj.y - pc.y;
            float dz = pj.z - pc.z;
            float dist = sqrtf(dx*dx + dy*dy + dz*dz);
            v0 += dx; v1 += dy; v2 += dz; v3 += dist;
            pxx += dx*dx; pxy += dx*dy; pxz += dx*dz; pxw += dx*dist;
            pyy += dy*dy; pyz += dy*dz; pyw += dy*dist;
            pzz += dz*dz; pzw += dz*dist; pww += dist*dist;
        }
    }

    // Deterministic butterfly reduction across warp 0's 32 lanes
    if (warp == 0) {
        float vals[14] = {v0,v1,v2,v3,pxx,pxy,pxz,pxw,pyy,pyz,pyw,pzz,pzw,pww};
#pragma unroll
        for (int c = 0; c < 14; c++) {
#pragma unroll
            for (int off = 16; off > 0; off >>= 1)
                vals[c] += __shfl_xor_sync(0xFFFFFFFFu, vals[c], off);
        }
        if (lane == 0) {
#pragma unroll
            for (int c = 0; c < 14; c++)
                g_part[blockIdx.x*14 + c] = vals[c];
        }
    }
}

// ---------------------------------------------------------------------------
// Kernel 2: fold BatchNorm into per-channel affine (deterministic, double)
// ---------------------------------------------------------------------------
__global__ void stats_kernel(const float* __restrict__ W,
                             const float* __restrict__ bias,
                             const float* __restrict__ gamma,
                             const float* __restrict__ beta) {
    __shared__ double mom[14];
    __shared__ double part[14][8];
    int tid = threadIdx.x;
    if (tid < 112) {
        int m = tid >> 3, sl = tid & 7;
        double a = 0.0;
        for (int blk = sl*128; blk < sl*128 + 128; blk++)
            a += (double)g_part[blk*14 + m];
        part[m][sl] = a;
    }
    __syncthreads();
    if (tid < 14) {
        double a = 0.0;
        for (int sl = 0; sl < 8; sl++) a += part[tid][sl];
        mom[tid] = a;
    }
    __syncthreads();
    if (tid < CO) {
        const double M = (double)M_EDGES;
        double m0=mom[0]/M, m1=mom[1]/M, m2=mom[2]/M, m3=mom[3]/M;
        double Sxx=mom[4]/M, Sxy=mom[5]/M, Sxz=mom[6]/M, Sxw=mom[7]/M;
        double Syy=mom[8]/M, Syz=mom[9]/M, Syw=mom[10]/M;
        double Szz=mom[11]/M, Szw=mom[12]/M, Sww=mom[13]/M;

        double w0 = W[tid*4+0], w1 = W[tid*4+1], w2 = W[tid*4+2], w3 = W[tid*4+3];
        double bb = bias[tid];
        double wm = w0*m0 + w1*m1 + w2*m2 + w3*m3;
        double mu = wm + bb;
        double E2 = w0*w0*Sxx + w1*w1*Syy + w2*w2*Szz + w3*w3*Sww
                  + 2.0*(w0*w1*Sxy + w0*w2*Sxz + w0*w3*Sxw
                       + w1*w2*Syz + w1*w3*Syw + w2*w3*Szw)
                  + 2.0*bb*wm + bb*bb;
        double var   = E2 - mu*mu;
        double scale = (double)gamma[tid] * rsqrt(var + 1e-5);
        g_A[tid*4+0] = (float)(scale * w0);
        g_A[tid*4+1] = (float)(scale * w1);
        g_A[tid*4+2] = (float)(scale * w2);
        g_A[tid*4+3] = (float)(scale * w3);
        g_C0[tid]    = (float)(scale * (bb - mu) + (double)beta[tid]);
    }
}

// ---------------------------------------------------------------------------
// Kernel 3: recompute edge features from indices, affine + relu + mean over k
// ---------------------------------------------------------------------------
__global__ void out_kernel(float* __restrict__ out) {
    __shared__ float4 shf[4*KNN];
    const int tid = threadIdx.x;
    const int pt0 = blockIdx.x * 4;
    const int b   = pt0 / NN;

    if (tid < 4*KNN) {
        const int lp = tid / KNN;          // local point 0..3
        const int s  = tid % KNN;          // neighbor slot
        const int gpt = pt0 + lp;
        const int i  = gpt % NN;
        float4 pi = g_pos4[b*NN + i];
        int    nj = g_nbr[gpt*KNN + s];
        float4 pj = g_pos4[b*NN + nj];
        float dx = pj.x - pi.x;
        float dy = pj.y - pi.y;
        float dz = pj.z - pi.z;
        float dist = sqrtf(dx*dx + dy*dy + dz*dz);
        shf[lp*KNN + s] = make_float4(dx, dy, dz, dist);
    }
    __syncthreads();

    const int lp = tid >> 6;    // local point 0..3
    const int c  = tid & 63;    // channel
    const float a0 = g_A[c*4+0], a1 = g_A[c*4+1], a2 = g_A[c*4+2], a3 = g_A[c*4+3];
    const float c0 = g_C0[c];

    float acc = 0.0f;
#pragma unroll
    for (int s = 0; s < KNN; s++) {
        float4 f = shf[lp*KNN + s];
        float v = a0*f.x + a1*f.y + a2*f.z + a3*f.w + c0;
        acc += fmaxf(v, 0.0f);   // relu; subsequent leaky(0.1) is identity on >=0
    }
    out[(size_t)(pt0 + lp)*CO + c] = acc * (1.0f / KNN);
}

// ---------------------------------------------------------------------------
extern "C" void kernel_launch(void* const* d_in, const int* in_sizes, int n_in,
                              void* d_out, int out_size) {
    const float* pos   = (const float*)d_in[1];
    const float* W     = (const float*)d_in[2];
    const float* bias  = (const float*)d_in[3];
    const float* gamma = (const float*)d_in[4];
    const float* beta  = (const float*)d_in[5];
    float* out = (float*)d_out;

    prep_kernel<<<(BB*NN + 255)/256, 256>>>(pos);
    knn_kernel<<<K1_GRID, K1_BLK>>>();
    stats_kernel<<<1, 128>>>(W, bias, gamma, beta);
    out_kernel<<<(BB*NN)/4, 256>>>(out);
}